// round 12
// baseline (speedup 1.0000x reference)
#include <cuda_runtime.h>
#include <math.h>

// ---------------- problem constants ----------------
#define Bb   4
#define Tt   6
#define Nn   1024
#define CSc  48
#define GSg  32
#define Hh   270
#define ATa  32
#define DAd  64
#define Ee   32
#define Ll   32
#define EDd  400
#define OUTo 4000
#define BT   (Bb*Tt)        // 24
#define BT2  (Bb*(Tt-1))    // 20
#define H3   (3*Hh)         // 810
#define H4   (4*Hh)         // 1080
#define XCOLS (BT*CSc)      // 1152
#define KV2  302            // packed cols: k(32) | v(270)

// attention batch mapping: z = b*(Tt-1) + (t-1)  (b-major)
#define ZBT(z) (((z) / (Tt-1)) * Tt + 1 + (z) % (Tt-1))

// ---------------- device scratch ----------------
__device__ float g_X   [Nn*XCOLS];
__device__ float g_S   [Nn*XCOLS];
__device__ float g_co  [BT*Nn*GSg];
__device__ float g_no  [BT*Nn*GSg];
__device__ float g_qin [BT*Nn*GSg];
__device__ float g_q   [BT2*Nn*ATa];     // compact m23 rows
__device__ float g_kv  [BT2*Nn*KV2];     // compact m23 rows: k|v
__device__ float g_gi  [BT*Nn*H3];       // scattered m1 rows
__device__ float g_packKV[33*KV2];
__device__ float g_G   [BT2*Nn*Nn];
__device__ float g_hm23[BT2*Nn*Hh];
__device__ float g_h   [Bb*Nn*Hh];
__device__ float g_gh  [Bb*Nn*H3];
__device__ signed char g_m1 [BT*Nn];
__device__ signed char g_m23[BT*Nn];
__device__ int   g_idx [BT2*Nn];
__device__ int   g_cnt [BT2];
__device__ int   g_idx1[BT*Nn];
__device__ int   g_cnt1[BT];
__device__ int   g_idx1t[Tt*Bb*Nn];
__device__ int   g_c1t [Tt];
__device__ float g_xe  [Bb*Ee*Ll*EDd];
__device__ float g_giL2[Bb*Ee*Ll*H4];    // [be][l][j][gate] (written by GEMM epi=4)
__device__ float g_W4  [Hh*H4];          // repacked lstm Whh: [k][j*4+gate]
__device__ float g_stack[Bb*(Ee+1)*Hh];
__device__ float g_wdc [Hh+1];
__device__ float g_vu  [Bb*(Ee+1)];
__device__ float g_o1  [Bb*Hh];
__device__ float g_opart[Bb*16*2*Hh];

__device__ __forceinline__ float sigf(float x){ return 1.f/(1.f+expf(-x)); }

// ---------------- 128x64 tiled SGEMM with gather/scatter ----------------
// epi: 0 none, 1 +bias, 2 tanh, 3 +bias,sigmoid, 4 +bias + gate-interleaved store
#define TKk 16
__global__ __launch_bounds__(256) void k_gemm(
    const float* __restrict__ A, const float* __restrict__ B,
    const float* __restrict__ bias, float* __restrict__ C,
    int M, int N, int K,
    int lda, int ldb, int ldc,
    long long sA, long long sB, long long sC,
    int epi, int mapAz, int mapBz,
    const int* __restrict__ gAidx, int gAs,
    const int* __restrict__ gBidx, int gBs,
    const int* __restrict__ sCidx, int sCs,
    const int* __restrict__ cntM, const int* __restrict__ cntK)
{
    int z = blockIdx.z;
    if (cntM) M = cntM[z];
    if (cntK) K = cntK[z];
    int row0 = blockIdx.y * 128;
    if (row0 >= M) return;
    int col0 = blockIdx.x * 64;

    int za = mapAz ? ZBT(z) : z;
    int zb = mapBz ? ZBT(z) : z;
    const float* Ab = A + (long long)za * sA;
    const float* Bbp = B + (long long)zb * sB;
    float* Cb = C + (long long)z * sC;
    const int* gA = gAidx ? gAidx + (long long)z * gAs : (const int*)0;
    const int* gB = gBidx ? gBidx + (long long)z * gBs : (const int*)0;
    const int* sCr = sCidx ? sCidx + (long long)z * sCs : (const int*)0;

    __shared__ __align__(16) float As[2][TKk][132];
    __shared__ __align__(16) float Bs[2][TKk][64];

    int tid = threadIdx.x;
    int ka = tid & 15, ra = tid >> 4;
    int cb = tid & 63, kb = tid >> 6;
    int tx = tid & 15, ty = tid >> 4;

    float acc[8][4] = {};
    int nk = (K + TKk - 1) / TKk;

    {
        #pragma unroll
        for (int i = 0; i < 8; i++) {
            int r = ra + i*16;
            int gr = row0 + r, kk = ka;
            float v = 0.f;
            if (gr < M && kk < K) {
                int ar = gA ? gA[gr] : gr;
                v = Ab[(long long)ar*lda + kk];
            }
            As[0][ka][r] = v;
        }
        #pragma unroll
        for (int i = 0; i < 4; i++) {
            int kk = kb + i*4;
            int c = col0 + cb;
            float v = 0.f;
            if (kk < K && c < N) {
                int br = gB ? gB[kk] : kk;
                v = Bbp[(long long)br*ldb + c];
            }
            Bs[0][kb + i*4][cb] = v;
        }
    }
    __syncthreads();

    for (int kt = 0; kt < nk; kt++) {
        int buf = kt & 1;
        if (kt + 1 < nk) {
            int k0 = (kt + 1) * TKk;
            #pragma unroll
            for (int i = 0; i < 8; i++) {
                int r = ra + i*16;
                int gr = row0 + r, kk = k0 + ka;
                float v = 0.f;
                if (gr < M && kk < K) {
                    int ar = gA ? gA[gr] : gr;
                    v = Ab[(long long)ar*lda + kk];
                }
                As[buf^1][ka][r] = v;
            }
            #pragma unroll
            for (int i = 0; i < 4; i++) {
                int kk = k0 + kb + i*4;
                int c = col0 + cb;
                float v = 0.f;
                if (kk < K && c < N) {
                    int br = gB ? gB[kk] : kk;
                    v = Bbp[(long long)br*ldb + c];
                }
                Bs[buf^1][kb + i*4][cb] = v;
            }
        }
        #pragma unroll
        for (int kk = 0; kk < TKk; kk++) {
            float4 a0 = *(const float4*)&As[buf][kk][ty*8];
            float4 a1 = *(const float4*)&As[buf][kk][ty*8 + 4];
            float4 b0 = *(const float4*)&Bs[buf][kk][tx*4];
            float av[8] = {a0.x,a0.y,a0.z,a0.w,a1.x,a1.y,a1.z,a1.w};
            float bv[4] = {b0.x,b0.y,b0.z,b0.w};
            #pragma unroll
            for (int i = 0; i < 8; i++)
                #pragma unroll
                for (int j = 0; j < 4; j++)
                    acc[i][j] += av[i]*bv[j];
        }
        __syncthreads();
    }

    #pragma unroll
    for (int i = 0; i < 8; i++) {
        int r = row0 + ty*8 + i;
        if (r >= M) continue;
        long long crow = sCr ? (long long)sCr[r]*ldc : (long long)r*ldc;
        #pragma unroll
        for (int j = 0; j < 4; j++) {
            int c = col0 + tx*4 + j;
            if (c >= N) continue;
            float v = acc[i][j];
            if (epi == 1 || epi == 3 || epi == 4) v += bias[c];
            if (epi == 2) v = tanhf(v);
            if (epi == 3) v = sigf(v);
            int cc = (epi == 4) ? ((c % Hh)*4 + c / Hh) : c;
            Cb[crow + cc] = v;
        }
    }
}

// ---------------- 64x64 tiled SGEMM ----------------
__global__ __launch_bounds__(256) void k_gemm64(
    const float* __restrict__ A, const float* __restrict__ B,
    const float* __restrict__ bias, float* __restrict__ C,
    int M, int N, int K,
    int lda, int ldb, int ldc,
    long long sA, long long sB, long long sC,
    int epi, int mapAz, int mapBz,
    const int* __restrict__ gAidx, int gAs,
    const int* __restrict__ gBidx, int gBs,
    const int* __restrict__ sCidx, int sCs,
    const int* __restrict__ cntM, const int* __restrict__ cntK)
{
    int z = blockIdx.z;
    if (cntM) M = cntM[z];
    if (cntK) K = cntK[z];
    int row0 = blockIdx.y * 64;
    if (row0 >= M) return;
    int col0 = blockIdx.x * 64;

    int za = mapAz ? ZBT(z) : z;
    int zb = mapBz ? ZBT(z) : z;
    const float* Ab = A + (long long)za * sA;
    const float* Bbp = B + (long long)zb * sB;
    float* Cb = C + (long long)z * sC;
    const int* gA = gAidx ? gAidx + (long long)z * gAs : (const int*)0;
    const int* gB = gBidx ? gBidx + (long long)z * gBs : (const int*)0;
    const int* sCr = sCidx ? sCidx + (long long)z * sCs : (const int*)0;

    __shared__ __align__(16) float As[2][TKk][68];
    __shared__ __align__(16) float Bs[2][TKk][64];

    int tid = threadIdx.x;
    int ka = tid & 15, ra = tid >> 4;
    int cb = tid & 63, kb = tid >> 6;
    int tx = tid & 15, ty = tid >> 4;

    float acc[4][4] = {};
    int nk = (K + TKk - 1) / TKk;

    {
        #pragma unroll
        for (int i = 0; i < 4; i++) {
            int r = ra + i*16;
            int gr = row0 + r, kk = ka;
            float v = 0.f;
            if (gr < M && kk < K) {
                int ar = gA ? gA[gr] : gr;
                v = Ab[(long long)ar*lda + kk];
            }
            As[0][ka][r] = v;
        }
        #pragma unroll
        for (int i = 0; i < 4; i++) {
            int kk = kb + i*4;
            int c = col0 + cb;
            float v = 0.f;
            if (kk < K && c < N) {
                int br = gB ? gB[kk] : kk;
                v = Bbp[(long long)br*ldb + c];
            }
            Bs[0][kb + i*4][cb] = v;
        }
    }
    __syncthreads();

    for (int kt = 0; kt < nk; kt++) {
        int buf = kt & 1;
        if (kt + 1 < nk) {
            int k0 = (kt + 1) * TKk;
            #pragma unroll
            for (int i = 0; i < 4; i++) {
                int r = ra + i*16;
                int gr = row0 + r, kk = k0 + ka;
                float v = 0.f;
                if (gr < M && kk < K) {
                    int ar = gA ? gA[gr] : gr;
                    v = Ab[(long long)ar*lda + kk];
                }
                As[buf^1][ka][r] = v;
            }
            #pragma unroll
            for (int i = 0; i < 4; i++) {
                int kk = k0 + kb + i*4;
                int c = col0 + cb;
                float v = 0.f;
                if (kk < K && c < N) {
                    int br = gB ? gB[kk] : kk;
                    v = Bbp[(long long)br*ldb + c];
                }
                Bs[buf^1][kb + i*4][cb] = v;
            }
        }
        #pragma unroll
        for (int kk = 0; kk < TKk; kk++) {
            float4 a0 = *(const float4*)&As[buf][kk][ty*4];
            float4 b0 = *(const float4*)&Bs[buf][kk][tx*4];
            float av[4] = {a0.x,a0.y,a0.z,a0.w};
            float bv[4] = {b0.x,b0.y,b0.z,b0.w};
            #pragma unroll
            for (int i = 0; i < 4; i++)
                #pragma unroll
                for (int j = 0; j < 4; j++)
                    acc[i][j] += av[i]*bv[j];
        }
        __syncthreads();
    }

    #pragma unroll
    for (int i = 0; i < 4; i++) {
        int r = row0 + ty*4 + i;
        if (r >= M) continue;
        long long crow = sCr ? (long long)sCr[r]*ldc : (long long)r*ldc;
        #pragma unroll
        for (int j = 0; j < 4; j++) {
            int c = col0 + tx*4 + j;
            if (c >= N) continue;
            float v = acc[i][j];
            if (epi == 1 || epi == 3) v += bias[c];
            if (epi == 2) v = tanhf(v);
            if (epi == 3) v = sigf(v);
            Cb[crow + c] = v;
        }
    }
}

// ---------------- input build ----------------
__global__ void k_build_X(const int* __restrict__ code_x, const int* __restrict__ neigh,
                          const float* __restrict__ c_emb, const float* __restrict__ n_emb)
{
    int idx = blockIdx.x * blockDim.x + threadIdx.x;
    if (idx >= Nn * XCOLS) return;
    int n  = idx / XCOLS;
    int r  = idx % XCOLS;
    int bt = r / CSc;
    int c  = r % CSc;
    float cx = (float)code_x[bt*Nn + n];
    float nx = (float)neigh [bt*Nn + n];
    g_X[idx] = cx * c_emb[n*CSc + c] + nx * n_emb[n*CSc + c];
}

__global__ __launch_bounds__(288) void k_spmm(const float* __restrict__ adj)
{
    int m = blockIdx.x;
    int tid = threadIdx.x;
    __shared__ float arow[Nn];
    for (int i = tid; i < Nn; i += 288) arow[i] = adj[(long long)m*Nn + i];
    __syncthreads();
    float acc0 = 0.f, acc1 = 0.f, acc2 = 0.f, acc3 = 0.f;
    for (int n = 0; n < Nn; n++) {
        float a = arow[n];
        if (a != 0.f) {
            const float* xr = g_X + (long long)n * XCOLS;
            acc0 += a * xr[tid];
            acc1 += a * xr[tid + 288];
            acc2 += a * xr[tid + 576];
            acc3 += a * xr[tid + 864];
        }
    }
    float* sr = g_S + (long long)m * XCOLS;
    sr[tid] = acc0; sr[tid+288] = acc1; sr[tid+576] = acc2; sr[tid+864] = acc3;
}

__global__ void k_masks(const int* __restrict__ divided)
{
    int i = blockIdx.x * blockDim.x + threadIdx.x;
    if (i >= BT*Nn) return;
    g_m1 [i] = (divided[3*i]     > 0) ? 1 : 0;
    g_m23[i] = (divided[3*i + 1] > 0 || divided[3*i + 2] > 0) ? 1 : 0;
}

__global__ __launch_bounds__(1024) void k_compact()
{
    int z = blockIdx.x;
    int bt = ZBT(z);
    int n = threadIdx.x;
    __shared__ int warpCnt[32];
    int m = g_m23[bt*Nn + n];
    unsigned bal = __ballot_sync(0xffffffffu, m != 0);
    int lane = n & 31, w = n >> 5;
    int pre = __popc(bal & ((1u << lane) - 1u));
    if (lane == 0) warpCnt[w] = __popc(bal);
    __syncthreads();
    if (w == 0) {
        int v = warpCnt[lane];
        #pragma unroll
        for (int o = 1; o < 32; o <<= 1) {
            int u = __shfl_up_sync(0xffffffffu, v, o);
            if (lane >= o) v += u;
        }
        warpCnt[lane] = v;
    }
    __syncthreads();
    int base = (w == 0) ? 0 : warpCnt[w - 1];
    if (m) g_idx[z*Nn + base + pre] = n;
    if (n == 1023) g_cnt[z] = warpCnt[31];
}

__global__ __launch_bounds__(1024) void k_compact1()
{
    int bt = blockIdx.x;
    int n = threadIdx.x;
    __shared__ int warpCnt[32];
    int m = g_m1[bt*Nn + n];
    unsigned bal = __ballot_sync(0xffffffffu, m != 0);
    int lane = n & 31, w = n >> 5;
    int pre = __popc(bal & ((1u << lane) - 1u));
    if (lane == 0) warpCnt[w] = __popc(bal);
    __syncthreads();
    if (w == 0) {
        int v = warpCnt[lane];
        #pragma unroll
        for (int o = 1; o < 32; o <<= 1) {
            int u = __shfl_up_sync(0xffffffffu, v, o);
            if (lane >= o) v += u;
        }
        warpCnt[lane] = v;
    }
    __syncthreads();
    int base = (w == 0) ? 0 : warpCnt[w - 1];
    if (m) g_idx1[bt*Nn + base + pre] = n;
    if (n == 1023) g_cnt1[bt] = warpCnt[31];
}

__global__ __launch_bounds__(1024) void k_compact1t()
{
    int t = blockIdx.x;
    int n = threadIdx.x;
    int lane = n & 31, w = n >> 5;
    __shared__ int warpCnt[32];
    __shared__ int baseAcc;
    if (n == 0) baseAcc = 0;
    __syncthreads();
    for (int b = 0; b < Bb; b++) {
        int bt = b*Tt + t;
        int m = g_m1[bt*Nn + n];
        unsigned bal = __ballot_sync(0xffffffffu, m != 0);
        int pre = __popc(bal & ((1u << lane) - 1u));
        if (lane == 0) warpCnt[w] = __popc(bal);
        __syncthreads();
        if (w == 0) {
            int v = warpCnt[lane];
            #pragma unroll
            for (int o = 1; o < 32; o <<= 1) {
                int u = __shfl_up_sync(0xffffffffu, v, o);
                if (lane >= o) v += u;
            }
            warpCnt[lane] = v;
        }
        __syncthreads();
        int base = baseAcc + ((w == 0) ? 0 : warpCnt[w - 1]);
        if (m) g_idx1t[t*(Bb*Nn) + base + pre] = b*Nn + n;
        __syncthreads();
        if (n == 0) baseAcc += warpCnt[31];
        __syncthreads();
    }
    if (n == 0) g_c1t[t] = baseAcc;
}

__global__ void k_co_no(const int* __restrict__ code_x, const int* __restrict__ neigh,
                        const float* __restrict__ c_emb, const float* __restrict__ n_emb,
                        const float* __restrict__ Wg, const float* __restrict__ bg)
{
    int bt = blockIdx.x;
    int n  = blockIdx.y * 8 + threadIdx.y;
    int g  = threadIdx.x;
    __shared__ float Wgs[CSc][GSg];
    int tid = threadIdx.y * 32 + threadIdx.x;
    for (int i = tid; i < CSc*GSg; i += 256) Wgs[i / GSg][i % GSg] = Wg[i];
    __syncthreads();
    const float* Srow = g_S + (long long)n * XCOLS + bt * CSc;
    float a1 = 0.f, a2 = 0.f;
    #pragma unroll
    for (int c = 0; c < CSc; c++) {
        float s = Srow[c];
        float w = Wgs[c][g];
        a1 += (c_emb[n*CSc + c] + s) * w;
        a2 += (n_emb[n*CSc + c] + s) * w;
    }
    float cx = (float)code_x[bt*Nn + n];
    float nx = (float)neigh [bt*Nn + n];
    float co = cx * a1 + bg[g];
    float no = nx * a2 + bg[g];
    co = (co >= 0.f) ? co : 0.01f * co;
    no = (no >= 0.f) ? no : 0.01f * no;
    long long o = ((long long)bt*Nn + n) * GSg + g;
    g_co[o] = co;
    g_no[o] = no;
}

__global__ void k_qin(const int* __restrict__ divided, const float* __restrict__ u_emb)
{
    int idx = blockIdx.x * blockDim.x + threadIdx.x;
    if (idx >= BT*Nn*GSg) return;
    int g  = idx % GSg;
    int bn = idx / GSg;
    int n  = bn % Nn;
    int bt = bn / Nn;
    int t  = bt % Tt;
    float v;
    if (divided[bn*3 + 2] > 0)       v = u_emb[n*GSg + g];
    else if (t > 0)                  v = g_no[((long long)(bt-1)*Nn + n)*GSg + g];
    else                             v = 0.f;
    g_qin[idx] = v;
}

__global__ void k_packKV(const float* __restrict__ Wk, const float* __restrict__ bk,
                         const float* __restrict__ Wv, const float* __restrict__ bv)
{
    int idx = blockIdx.x * blockDim.x + threadIdx.x;
    if (idx >= 33*KV2) return;
    int r = idx / KV2, c = idx % KV2;
    float v;
    if (r < 32) {
        if (c < 32) v = Wk[r*ATa + c];
        else        v = Wv[r*Hh + (c - 32)];
    } else {
        if (c < 32) v = bk[c];
        else        v = bv[c - 32];
    }
    g_packKV[idx] = v;
}

// repack lstm Whh to [k][j*4+gate]
__global__ void k_packWhh(const float* __restrict__ Whh)
{
    int idx = blockIdx.x * blockDim.x + threadIdx.x;
    if (idx >= Hh*H4) return;
    int g = idx & 3;
    int rem = idx >> 2;
    int j = rem % Hh;
    int k2 = rem / Hh;
    g_W4[idx] = Whh[k2*H4 + g*Hh + j];
}

// ---------------- fused compacted score + softmax ----------------
__global__ __launch_bounds__(256) void k_score_softmax()
{
    int z = blockIdx.y;
    int cq = g_cnt[z];
    int qr0 = blockIdx.x * 64;
    if (qr0 >= cq) return;
    const float* qp = g_q + (long long)z*Nn*ATa;
    const float* kb = g_kv + (long long)z*Nn*KV2;
    float* G = g_G + (long long)z * Nn * Nn;

    __shared__ float qs[64][33];
    __shared__ float ks[64][33];
    __shared__ float pmax[16][64];
    __shared__ float rowmax[64];

    int tid = threadIdx.x;
    int tx = tid & 15, ty = tid >> 4;

    for (int i = tid; i < 64*32; i += 256) {
        int r = i >> 5, a = i & 31;
        int gq = qr0 + r;
        qs[r][a] = (gq < cq) ? qp[(long long)gq*ATa + a] : 0.f;
    }

    float tmax[4] = {-1e30f, -1e30f, -1e30f, -1e30f};
    const float scale = 0.17677669529663687f;

    for (int j0 = 0; j0 < cq; j0 += 64) {
        __syncthreads();
        for (int i = tid; i < 64*32; i += 256) {
            int r = i >> 5, a = i & 31;
            int gk = j0 + r;
            ks[r][a] = (gk < cq) ? kb[(long long)gk*KV2 + a] : 0.f;
        }
        __syncthreads();
        float acc[4][4] = {};
        #pragma unroll
        for (int a = 0; a < 32; a++) {
            float av[4], bv[4];
            #pragma unroll
            for (int i = 0; i < 4; i++) av[i] = qs[ty*4+i][a];
            #pragma unroll
            for (int j = 0; j < 4; j++) bv[j] = ks[tx*4+j][a];
            #pragma unroll
            for (int i = 0; i < 4; i++)
                #pragma unroll
                for (int j = 0; j < 4; j++) acc[i][j] += av[i]*bv[j];
        }
        #pragma unroll
        for (int i = 0; i < 4; i++) {
            int gr = qr0 + ty*4 + i;
            if (gr >= cq) continue;
            #pragma unroll
            for (int j = 0; j < 4; j++) {
                int gc = j0 + tx*4 + j;
                if (gc >= cq) continue;
                float v = acc[i][j] * scale;
                G[(long long)gr*Nn + gc] = v;
                tmax[i] = fmaxf(tmax[i], v);
            }
        }
    }
    #pragma unroll
    for (int i = 0; i < 4; i++) pmax[tx][ty*4 + i] = tmax[i];
    __syncthreads();
    if (tid < 64) {
        float m = -1e30f;
        #pragma unroll
        for (int x = 0; x < 16; x++) m = fmaxf(m, pmax[x][tid]);
        rowmax[tid] = m;
    }
    __syncthreads();

    int row = tid >> 2, l4 = tid & 3;
    int gr = qr0 + row;
    float s = 0.f;
    if (gr < cq) {
        float m = rowmax[row];
        for (int c = l4; c < cq; c += 4) {
            float e = expf(G[(long long)gr*Nn + c] - m);
            G[(long long)gr*Nn + c] = e;
            s += e;
        }
    }
    s += __shfl_xor_sync(0xffffffffu, s, 1);
    s += __shfl_xor_sync(0xffffffffu, s, 2);
    if (gr < cq) {
        float inv = 1.f / s;
        for (int c = l4; c < cq; c += 4)
            G[(long long)gr*Nn + c] *= inv;
    }
}

// ---------------- GRU combine ----------------
__global__ void k_gru_combine(int t, const float* __restrict__ gbhh)
{
    int idx = blockIdx.x * blockDim.x + threadIdx.x;
    if (idx >= Bb*Nn*Hh) return;
    int j  = idx % Hh;
    int bn = idx / Hh;
    int n  = bn % Nn;
    int b  = bn / Nn;
    int bt = b*Tt + t;
    int mi = bt*Nn + n;
    float hv = 0.f;
    if (t > 0 && g_m23[mi]) {
        hv = g_hm23[((long long)(b*(Tt-1) + (t-1))*Nn + n) * Hh + j];
    } else if (g_m1[mi]) {
        const float* gir = g_gi + ((long long)bt*Nn + n)*H3;
        float g0, g1, g2;
        if (t == 0) { g0 = gbhh[j]; g1 = gbhh[Hh + j]; g2 = gbhh[2*Hh + j]; }
        else {
            const float* ghr = g_gh + (long long)bn * H3;
            g0 = ghr[j]; g1 = ghr[Hh + j]; g2 = ghr[2*Hh + j];
        }
        float r  = sigf(gir[j]        + g0);
        float zz = sigf(gir[Hh + j]   + g1);
        float nn = tanhf(gir[2*Hh + j] + r * g2);
        float hp = (t == 0) ? 0.f : g_h[idx];
        hv = (1.f - zz) * nn + zz * hp;
    }
    g_h[idx] = hv;
}

// parallel outlast
__global__ __launch_bounds__(288) void k_outlast1()
{
    int b = blockIdx.x, p = blockIdx.y, j = threadIdx.x;
    if (j >= Hh) return;
    float mx1 = -1e38f, mx23 = -1e38f;
    int mbase = (b*Tt + (Tt-1)) * Nn;
    int n0 = p * 64;
    for (int n = n0; n < n0 + 64; n++) {
        float hv = g_h[((long long)b*Nn + n)*Hh + j];
        if (g_m1 [mbase + n]) mx1  = fmaxf(mx1,  hv);
        if (g_m23[mbase + n]) mx23 = fmaxf(mx23, hv);
    }
    g_opart[((b*16 + p)*2    )*Hh + j] = mx1;
    g_opart[((b*16 + p)*2 + 1)*Hh + j] = mx23;
}

__global__ __launch_bounds__(288) void k_outlast2()
{
    int b = blockIdx.x, j = threadIdx.x;
    if (j >= Hh) return;
    float mx1 = -1e38f, mx23 = -1e38f;
    #pragma unroll
    for (int p = 0; p < 16; p++) {
        mx1  = fmaxf(mx1,  g_opart[((b*16 + p)*2    )*Hh + j]);
        mx23 = fmaxf(mx23, g_opart[((b*16 + p)*2 + 1)*Hh + j]);
    }
    float o = 0.f;
    if (mx1  > -1e37f) o += mx1;
    if (mx23 > -1e37f) o += mx23;
    g_stack[(long long)b*(Ee+1)*Hh + j] = o;
}

// ---------------- event LSTM ----------------
__global__ void k_evgather(const int* __restrict__ events, const float* __restrict__ Eemb)
{
    int idx = blockIdx.x * blockDim.x + threadIdx.x;
    if (idx >= Bb*Ee*Ll*EDd) return;
    int d   = idx % EDd;
    int rem = idx / EDd;
    int l   = rem % Ll;
    int be  = rem / Ll;
    int b   = be / Ee, e = be % Ee;
    int ev  = events[((b*Tt + (Tt-1))*Ee + e)*Ll + l];
    g_xe[idx] = Eemb[(long long)ev*EDd + d];
}

// column-parallel persistent LSTM: 2 rows per block, 64 blocks, 544 threads.
// Matvec: two k-halves. Group 0 = threads [0,270): col j = tid, k in [0,135).
// Group 1 = threads [272,542): col j = tid-272, k in [135,270).
// Each thread: 1 LDG.128 per k (all 4 gates of col j) + h2 LDS + 8 FMA.
// Partials combined in smem; epilogue thread (er,ej) adds halves + prefetched giL2.
#define LB9 9
__global__ __launch_bounds__(544) void k_lstm3()
{
    __shared__ __align__(8)  float2 h2[Hh];
    __shared__ __align__(16) float4 a_sh[2][2][Hh];  // [khalf][row][j] = 4 gates
    int tid = threadIdx.x;
    int row0 = blockIdx.x * 2;

    int mg, mj;
    if (tid < Hh)                    { mg = 0; mj = tid; }
    else if (tid >= 272 && tid < 542){ mg = 1; mj = tid - 272; }
    else                             { mg = -1; mj = 0; }

    int er = tid / Hh;               // epilogue row (valid tid<540)
    int ej = tid - er * Hh;
    float cs = 0.f;

    if (tid < Hh) h2[tid] = make_float2(0.f, 0.f);
    __syncthreads();

    const float4* W4v = (const float4*)g_W4;   // [k][j] float4
    int kbase = mg * 135;

    for (int l = 0; l < Ll; l++) {
        // prefetch epilogue gates (independent of matvec)
        float4 gl = make_float4(0.f, 0.f, 0.f, 0.f);
        if (tid < 2*Hh)
            gl = *(const float4*)&g_giL2[(((long long)(row0 + er)*Ll + l)*Hh + ej)*4];

        if (mg >= 0) {
            float4 acc0 = make_float4(0.f,0.f,0.f,0.f);
            float4 acc1 = make_float4(0.f,0.f,0.f,0.f);
            #pragma unroll
            for (int k0 = 0; k0 < 135; k0 += LB9) {
                float4 wv[LB9];
                float2 hv[LB9];
                #pragma unroll
                for (int u = 0; u < LB9; u++) wv[u] = __ldg(&W4v[(long long)(kbase + k0 + u)*Hh + mj]);
                #pragma unroll
                for (int u = 0; u < LB9; u++) hv[u] = h2[kbase + k0 + u];
                #pragma unroll
                for (int u = 0; u < LB9; u++) {
                    acc0.x += hv[u].x*wv[u].x; acc0.y += hv[u].x*wv[u].y;
                    acc0.z += hv[u].x*wv[u].z; acc0.w += hv[u].x*wv[u].w;
                    acc1.x += hv[u].y*wv[u].x; acc1.y += hv[u].y*wv[u].y;
                    acc1.z += hv[u].y*wv[u].z; acc1.w += hv[u].y*wv[u].w;
                }
            }
            a_sh[mg][0][mj] = acc0;
            a_sh[mg][1][mj] = acc1;
        }
        __syncthreads();
        if (tid < 2*Hh) {
            float4 pa = a_sh[0][er][ej];
            float4 pb = a_sh[1][er][ej];
            float gi_ = pa.x + pb.x + gl.x;
            float gf  = pa.y + pb.y + gl.y;
            float gg  = pa.z + pb.z + gl.z;
            float go  = pa.w + pb.w + gl.w;
            cs = sigf(gf)*cs + sigf(gi_)*tanhf(gg);
            float hn = sigf(go)*tanhf(cs);
            float* hp = (float*)&h2[ej];
            hp[er] = hn;
        }
        __syncthreads();
    }

    if (tid < 2*Hh) {
        int be = row0 + er;
        int b = be / Ee, e = be % Ee;
        float* hp = (float*)&h2[ej];
        g_stack[((long long)b*(Ee+1) + 1 + e)*Hh + ej] = hp[er];
    }
}

// ---------------- final dp attention + head ----------------
__global__ void k_wdctx(const float* __restrict__ Wd, const float* __restrict__ bd,
                        const float* __restrict__ ctx)
{
    int j = threadIdx.x;
    if (j < Hh) {
        float s = 0.f;
        for (int d = 0; d < DAd; d++) s += Wd[j*DAd + d] * ctx[d];
        g_wdc[j] = s;
    } else if (j == Hh) {
        float s = 0.f;
        for (int d = 0; d < DAd; d++) s += bd[d] * ctx[d];
        g_wdc[Hh] = s;
    }
}

__global__ void k_dp1()
{
    int b = blockIdx.x, s = blockIdx.y;
    const float* x = g_stack + ((long long)b*(Ee+1) + s) * Hh;
    __shared__ float red[256];
    int tid = threadIdx.x;
    float acc = 0.f;
    for (int h = tid; h < Hh; h += 256) acc += x[h] * g_wdc[h];
    red[tid] = acc; __syncthreads();
    for (int st = 128; st > 0; st >>= 1) { if (tid < st) red[tid] += red[tid + st]; __syncthreads(); }
    if (tid == 0) g_vu[b*(Ee+1) + s] = red[0] + g_wdc[Hh];
}

__global__ void k_dp2()
{
    int b = blockIdx.x, j = threadIdx.x;
    __shared__ float sm[Ee+1];
    if (j == 0) {
        float mx = -1e38f;
        for (int s = 0; s < Ee+1; s++) mx = fmaxf(mx, g_vu[b*(Ee+1) + s]);
        float sum = 0.f;
        for (int s = 0; s < Ee+1; s++) { float e = expf(g_vu[b*(Ee+1) + s] - mx); sm[s] = e; sum += e; }
        float inv = 1.f / sum;
        for (int s = 0; s < Ee+1; s++) sm[s] *= inv;
    }
    __syncthreads();
    if (j < Hh) {
        float acc = 0.f;
        for (int s = 0; s < Ee+1; s++) acc += sm[s] * g_stack[((long long)b*(Ee+1) + s)*Hh + j];
        g_o1[b*Hh + j] = acc;
    }
}

// ---------------- host driver ----------------
extern "C" void kernel_launch(void* const* d_in, const int* in_sizes, int n_in,
                              void* d_out, int out_size)
{
    const int*   code_x = (const int*)  d_in[0];
    const int*   divided= (const int*)  d_in[1];
    const int*   neigh  = (const int*)  d_in[2];
    const int*   events = (const int*)  d_in[4];
    const float* c_emb  = (const float*)d_in[5];
    const float* n_emb  = (const float*)d_in[6];
    const float* u_emb  = (const float*)d_in[7];
    const float* adj    = (const float*)d_in[8];
    const float* Wg     = (const float*)d_in[9];
    const float* bg     = (const float*)d_in[10];
    const float* gWih   = (const float*)d_in[11];
    const float* gWhh   = (const float*)d_in[12];
    const float* gbih   = (const float*)d_in[13];
    const float* gbhh   = (const float*)d_in[14];
    const float* Wq     = (const float*)d_in[15];
    const float* bq     = (const float*)d_in[16];
    const float* Wk     = (const float*)d_in[17];
    const float* bk     = (const float*)d_in[18];
    const float* Wv     = (const float*)d_in[19];
    const float* bv     = (const float*)d_in[20];
    const float* Wd     = (const float*)d_in[21];
    const float* bd     = (const float*)d_in[22];
    const float* ctx    = (const float*)d_in[23];
    const float* Eemb   = (const float*)d_in[24];
    const float* lWih   = (const float*)d_in[25];
    const float* lWhh   = (const float*)d_in[26];
    const float* lb     = (const float*)d_in[27];
    const float* Wc     = (const float*)d_in[28];
    const float* bc     = (const float*)d_in[29];
    float* out = (float*)d_out;

    float *pco, *pqin, *pq, *pkv, *pgi, *pKV, *pG, *phm, *ph, *pgh, *pxe, *pgiL2, *po1;
    int *pidx, *pcnt, *pidx1, *pcnt1, *pidx1t, *pc1t;
    cudaGetSymbolAddress((void**)&pco,   g_co);
    cudaGetSymbolAddress((void**)&pqin,  g_qin);
    cudaGetSymbolAddress((void**)&pq,    g_q);
    cudaGetSymbolAddress((void**)&pkv,   g_kv);
    cudaGetSymbolAddress((void**)&pgi,   g_gi);
    cudaGetSymbolAddress((void**)&pKV,   g_packKV);
    cudaGetSymbolAddress((void**)&pG,    g_G);
    cudaGetSymbolAddress((void**)&phm,   g_hm23);
    cudaGetSymbolAddress((void**)&ph,    g_h);
    cudaGetSymbolAddress((void**)&pgh,   g_gh);
    cudaGetSymbolAddress((void**)&pxe,   g_xe);
    cudaGetSymbolAddress((void**)&pgiL2, g_giL2);
    cudaGetSymbolAddress((void**)&po1,   g_o1);
    cudaGetSymbolAddress((void**)&pidx,  g_idx);
    cudaGetSymbolAddress((void**)&pcnt,  g_cnt);
    cudaGetSymbolAddress((void**)&pidx1, g_idx1);
    cudaGetSymbolAddress((void**)&pcnt1, g_cnt1);
    cudaGetSymbolAddress((void**)&pidx1t,g_idx1t);
    cudaGetSymbolAddress((void**)&pc1t,  g_c1t);

    static cudaStream_t s2 = 0;
    static cudaEvent_t evF = 0, evJ = 0;
    if (!s2) {
        cudaStreamCreateWithFlags(&s2, cudaStreamNonBlocking);
        cudaEventCreateWithFlags(&evF, cudaEventDisableTiming);
        cudaEventCreateWithFlags(&evJ, cudaEventDisableTiming);
    }

    // fork: event-LSTM chain on s2 (independent until dp1)
    cudaEventRecord(evF, 0);
    cudaStreamWaitEvent(s2, evF, 0);
    k_packWhh<<<(Hh*H4 + 255)/256, 256, 0, s2>>>(lWhh);
    k_evgather<<<(Bb*Ee*Ll*EDd + 255)/256, 256, 0, s2>>>(events, Eemb);
    k_gemm<<<dim3(17, 32, 1), 256, 0, s2>>>(pxe, lWih, lb, pgiL2,
        Bb*Ee*Ll, H4, EDd, EDd, H4, H4, 0,0,0, 4, 0,0, 0,0, 0,0, 0,0, 0,0);
    k_lstm3<<<(Bb*Ee)/2, 544, 0, s2>>>();
    cudaEventRecord(evJ, s2);

    // main stream
    k_build_X<<<(Nn*XCOLS + 255)/256, 256>>>(code_x, neigh, c_emb, n_emb);
    k_masks  <<<(BT*Nn + 255)/256, 256>>>(divided);
    k_wdctx  <<<1, 288>>>(Wd, bd, ctx);
    k_compact  <<<BT2, 1024>>>();
    k_compact1 <<<BT,  1024>>>();
    k_compact1t<<<Tt,  1024>>>();
    k_packKV<<<(33*KV2 + 255)/256, 256>>>(Wk, bk, Wv, bv);

    k_spmm<<<Nn, 288>>>(adj);
    k_co_no<<<dim3(BT, Nn/8), dim3(32,8)>>>(code_x, neigh, c_emb, n_emb, Wg, bg);
    k_qin  <<<(BT*Nn*GSg + 255)/256, 256>>>(divided, u_emb);

    // gi projection: m1 rows only, scattered
    k_gemm<<<dim3(13, 8, BT), 256>>>(pco, gWih, gbih, pgi,
        Nn, H3, GSg, GSg, H3, H3,
        (long long)Nn*GSg, 0, (long long)Nn*H3,
        1, 0,0, pidx1, Nn, 0,0, pidx1, Nn, pcnt1, 0);

    // k|v projection: m23 rows only (t>=1), stored COMPACT
    k_gemm<<<dim3(5, 8, BT2), 256>>>(pco, pKV, pKV + 32*KV2, pkv,
        Nn, KV2, GSg, GSg, KV2, KV2,
        (long long)Nn*GSg, 0, (long long)Nn*KV2,
        1, 1,0, pidx, Nn, 0,0, 0,0, pcnt, 0);

    // q projection, compact m23 rows
    k_gemm64<<<dim3(1, 16, BT2), 256>>>(pqin, Wq, bq, pq,
        Nn, ATa, GSg, GSg, ATa, ATa,
        (long long)Nn*GSg, 0, (long long)Nn*ATa,
        1, 1,0, pidx, Nn, 0,0, 0,0, pcnt, 0);

    // attention: fused score+softmax (compact k), then tanh(P @ V) scattered
    k_score_softmax<<<dim3(16, BT2), 256>>>();
    k_gemm<<<dim3(5, 8, BT2), 256>>>(pG, pkv + 32, 0, phm,
        Nn, Hh, Nn, Nn, KV2, Hh,
        (long long)Nn*Nn, (long long)Nn*KV2, (long long)Nn*Hh,
        2, 0,0, 0,0, 0,0, pidx, Nn, pcnt, pcnt);

    // GRU: t=0 bias-only; t>=1 gh GEMM compacted to m1 rows
    k_gru_combine<<<(Bb*Nn*Hh + 255)/256, 256>>>(0, gbhh);
    for (int t = 1; t < Tt; t++) {
        k_gemm64<<<dim3(13, 64, 1), 256>>>(ph, gWhh, gbhh, pgh,
            Bb*Nn, H3, Hh, Hh, H3, H3, 0,0,0,
            1, 0,0, pidx1t + t*(Bb*Nn), 0, 0,0, pidx1t + t*(Bb*Nn), 0, pc1t + t, 0);
        k_gru_combine<<<(Bb*Nn*Hh + 255)/256, 256>>>(t, gbhh);
    }
    k_outlast1<<<dim3(Bb, 16), 288>>>();
    k_outlast2<<<Bb, 288>>>();

    // join LSTM chain, then dp attention + classifier
    cudaStreamWaitEvent(0, evJ, 0);
    k_dp1<<<dim3(Bb, Ee+1), 256>>>();
    k_dp2<<<Bb, 288>>>();
    k_gemm64<<<dim3(63, 1, 1), 256>>>(po1, Wc, bc, out,
        Bb, OUTo, Hh, Hh, OUTo, OUTo, 0,0,0, 3, 0,0, 0,0, 0,0, 0,0, 0,0);
}

// round 13
// speedup vs baseline: 1.1204x; 1.1204x over previous
#include <cuda_runtime.h>
#include <math.h>

// ---------------- problem constants ----------------
#define Bb   4
#define Tt   6
#define Nn   1024
#define CSc  48
#define GSg  32
#define Hh   270
#define ATa  32
#define DAd  64
#define Ee   32
#define Ll   32
#define EDd  400
#define OUTo 4000
#define BT   (Bb*Tt)        // 24
#define BT2  (Bb*(Tt-1))    // 20
#define H3   (3*Hh)         // 810
#define H4   (4*Hh)         // 1080
#define XCOLS (BT*CSc)      // 1152
#define KV2  302            // packed cols: k(32) | v(270)

// attention batch mapping: z = b*(Tt-1) + (t-1)  (b-major)
#define ZBT(z) (((z) / (Tt-1)) * Tt + 1 + (z) % (Tt-1))

// ---------------- device scratch ----------------
__device__ float g_X   [Nn*XCOLS];
__device__ float g_S   [Nn*XCOLS];
__device__ float g_co  [BT*Nn*GSg];
__device__ float g_no  [BT*Nn*GSg];
__device__ float g_qin [BT*Nn*GSg];
__device__ float g_q   [BT2*Nn*ATa];
__device__ float g_kv  [BT2*Nn*KV2];
__device__ float g_gi  [BT*Nn*H3];
__device__ float g_packKV[33*KV2];
__device__ float g_G   [BT2*Nn*Nn];
__device__ float g_rsum[BT2*Nn];
__device__ float g_hm23[BT2*Nn*Hh];
__device__ float g_h   [Bb*Nn*Hh];
__device__ float g_gh  [Bb*Nn*H3];
__device__ signed char g_m1 [BT*Nn];
__device__ signed char g_m23[BT*Nn];
__device__ int   g_idx [BT2*Nn];
__device__ int   g_cnt [BT2];
__device__ int   g_idx1[BT*Nn];
__device__ int   g_cnt1[BT];
__device__ int   g_idx1t[Tt*Bb*Nn];
__device__ int   g_c1t [Tt];
__device__ float g_xe  [Bb*Ee*Ll*EDd];
__device__ float g_giL2[Bb*Ee*Ll*H4];
__device__ float g_W4  [Hh*H4];
__device__ float g_stack[Bb*(Ee+1)*Hh];
__device__ float g_wdc [Hh+1];
__device__ float g_vu  [Bb*(Ee+1)];
__device__ float g_o1  [Bb*Hh];
__device__ float g_opart[Bb*16*2*Hh];

__device__ __forceinline__ float sigf(float x){ return 1.f/(1.f+expf(-x)); }

// ---------------- 128x64 tiled SGEMM with gather/scatter ----------------
// epi: 0 none, 1 +bias, 2 tanh, 3 +bias,sigmoid, 4 +bias gate-interleave,
//      5 tanh(acc / rsum[row])
#define TKk 16
__global__ __launch_bounds__(256) void k_gemm(
    const float* __restrict__ A, const float* __restrict__ B,
    const float* __restrict__ bias, float* __restrict__ C,
    int M, int N, int K,
    int lda, int ldb, int ldc,
    long long sA, long long sB, long long sC,
    int epi, int mapAz, int mapBz,
    const int* __restrict__ gAidx, int gAs,
    const int* __restrict__ gBidx, int gBs,
    const int* __restrict__ sCidx, int sCs,
    const int* __restrict__ cntM, const int* __restrict__ cntK,
    const float* __restrict__ rsum)
{
    int z = blockIdx.z;
    if (cntM) M = cntM[z];
    if (cntK) K = cntK[z];
    int row0 = blockIdx.y * 128;
    if (row0 >= M) return;
    int col0 = blockIdx.x * 64;

    int za = mapAz ? ZBT(z) : z;
    int zb = mapBz ? ZBT(z) : z;
    const float* Ab = A + (long long)za * sA;
    const float* Bbp = B + (long long)zb * sB;
    float* Cb = C + (long long)z * sC;
    const int* gA = gAidx ? gAidx + (long long)z * gAs : (const int*)0;
    const int* gB = gBidx ? gBidx + (long long)z * gBs : (const int*)0;
    const int* sCr = sCidx ? sCidx + (long long)z * sCs : (const int*)0;
    const float* rs = rsum ? rsum + (long long)z * Nn : (const float*)0;

    __shared__ __align__(16) float As[2][TKk][132];
    __shared__ __align__(16) float Bs[2][TKk][64];

    int tid = threadIdx.x;
    int ka = tid & 15, ra = tid >> 4;
    int cb = tid & 63, kb = tid >> 6;
    int tx = tid & 15, ty = tid >> 4;

    float acc[8][4] = {};
    int nk = (K + TKk - 1) / TKk;

    {
        #pragma unroll
        for (int i = 0; i < 8; i++) {
            int r = ra + i*16;
            int gr = row0 + r, kk = ka;
            float v = 0.f;
            if (gr < M && kk < K) {
                int ar = gA ? gA[gr] : gr;
                v = Ab[(long long)ar*lda + kk];
            }
            As[0][ka][r] = v;
        }
        #pragma unroll
        for (int i = 0; i < 4; i++) {
            int kk = kb + i*4;
            int c = col0 + cb;
            float v = 0.f;
            if (kk < K && c < N) {
                int br = gB ? gB[kk] : kk;
                v = Bbp[(long long)br*ldb + c];
            }
            Bs[0][kb + i*4][cb] = v;
        }
    }
    __syncthreads();

    for (int kt = 0; kt < nk; kt++) {
        int buf = kt & 1;
        if (kt + 1 < nk) {
            int k0 = (kt + 1) * TKk;
            #pragma unroll
            for (int i = 0; i < 8; i++) {
                int r = ra + i*16;
                int gr = row0 + r, kk = k0 + ka;
                float v = 0.f;
                if (gr < M && kk < K) {
                    int ar = gA ? gA[gr] : gr;
                    v = Ab[(long long)ar*lda + kk];
                }
                As[buf^1][ka][r] = v;
            }
            #pragma unroll
            for (int i = 0; i < 4; i++) {
                int kk = k0 + kb + i*4;
                int c = col0 + cb;
                float v = 0.f;
                if (kk < K && c < N) {
                    int br = gB ? gB[kk] : kk;
                    v = Bbp[(long long)br*ldb + c];
                }
                Bs[buf^1][kb + i*4][cb] = v;
            }
        }
        #pragma unroll
        for (int kk = 0; kk < TKk; kk++) {
            float4 a0 = *(const float4*)&As[buf][kk][ty*8];
            float4 a1 = *(const float4*)&As[buf][kk][ty*8 + 4];
            float4 b0 = *(const float4*)&Bs[buf][kk][tx*4];
            float av[8] = {a0.x,a0.y,a0.z,a0.w,a1.x,a1.y,a1.z,a1.w};
            float bv[4] = {b0.x,b0.y,b0.z,b0.w};
            #pragma unroll
            for (int i = 0; i < 8; i++)
                #pragma unroll
                for (int j = 0; j < 4; j++)
                    acc[i][j] += av[i]*bv[j];
        }
        __syncthreads();
    }

    #pragma unroll
    for (int i = 0; i < 8; i++) {
        int r = row0 + ty*8 + i;
        if (r >= M) continue;
        long long crow = sCr ? (long long)sCr[r]*ldc : (long long)r*ldc;
        float inv = (epi == 5) ? (1.f / rs[r]) : 1.f;
        #pragma unroll
        for (int j = 0; j < 4; j++) {
            int c = col0 + tx*4 + j;
            if (c >= N) continue;
            float v = acc[i][j];
            if (epi == 1 || epi == 3 || epi == 4) v += bias[c];
            if (epi == 2) v = tanhf(v);
            if (epi == 3) v = sigf(v);
            if (epi == 5) v = tanhf(v * inv);
            int cc = (epi == 4) ? ((c % Hh)*4 + c / Hh) : c;
            Cb[crow + cc] = v;
        }
    }
}

// ---------------- 64x64 tiled SGEMM ----------------
__global__ __launch_bounds__(256) void k_gemm64(
    const float* __restrict__ A, const float* __restrict__ B,
    const float* __restrict__ bias, float* __restrict__ C,
    int M, int N, int K,
    int lda, int ldb, int ldc,
    long long sA, long long sB, long long sC,
    int epi, int mapAz, int mapBz,
    const int* __restrict__ gAidx, int gAs,
    const int* __restrict__ gBidx, int gBs,
    const int* __restrict__ sCidx, int sCs,
    const int* __restrict__ cntM, const int* __restrict__ cntK)
{
    int z = blockIdx.z;
    if (cntM) M = cntM[z];
    if (cntK) K = cntK[z];
    int row0 = blockIdx.y * 64;
    if (row0 >= M) return;
    int col0 = blockIdx.x * 64;

    int za = mapAz ? ZBT(z) : z;
    int zb = mapBz ? ZBT(z) : z;
    const float* Ab = A + (long long)za * sA;
    const float* Bbp = B + (long long)zb * sB;
    float* Cb = C + (long long)z * sC;
    const int* gA = gAidx ? gAidx + (long long)z * gAs : (const int*)0;
    const int* gB = gBidx ? gBidx + (long long)z * gBs : (const int*)0;
    const int* sCr = sCidx ? sCidx + (long long)z * sCs : (const int*)0;

    __shared__ __align__(16) float As[2][TKk][68];
    __shared__ __align__(16) float Bs[2][TKk][64];

    int tid = threadIdx.x;
    int ka = tid & 15, ra = tid >> 4;
    int cb = tid & 63, kb = tid >> 6;
    int tx = tid & 15, ty = tid >> 4;

    float acc[4][4] = {};
    int nk = (K + TKk - 1) / TKk;

    {
        #pragma unroll
        for (int i = 0; i < 4; i++) {
            int r = ra + i*16;
            int gr = row0 + r, kk = ka;
            float v = 0.f;
            if (gr < M && kk < K) {
                int ar = gA ? gA[gr] : gr;
                v = Ab[(long long)ar*lda + kk];
            }
            As[0][ka][r] = v;
        }
        #pragma unroll
        for (int i = 0; i < 4; i++) {
            int kk = kb + i*4;
            int c = col0 + cb;
            float v = 0.f;
            if (kk < K && c < N) {
                int br = gB ? gB[kk] : kk;
                v = Bbp[(long long)br*ldb + c];
            }
            Bs[0][kb + i*4][cb] = v;
        }
    }
    __syncthreads();

    for (int kt = 0; kt < nk; kt++) {
        int buf = kt & 1;
        if (kt + 1 < nk) {
            int k0 = (kt + 1) * TKk;
            #pragma unroll
            for (int i = 0; i < 4; i++) {
                int r = ra + i*16;
                int gr = row0 + r, kk = k0 + ka;
                float v = 0.f;
                if (gr < M && kk < K) {
                    int ar = gA ? gA[gr] : gr;
                    v = Ab[(long long)ar*lda + kk];
                }
                As[buf^1][ka][r] = v;
            }
            #pragma unroll
            for (int i = 0; i < 4; i++) {
                int kk = k0 + kb + i*4;
                int c = col0 + cb;
                float v = 0.f;
                if (kk < K && c < N) {
                    int br = gB ? gB[kk] : kk;
                    v = Bbp[(long long)br*ldb + c];
                }
                Bs[buf^1][kb + i*4][cb] = v;
            }
        }
        #pragma unroll
        for (int kk = 0; kk < TKk; kk++) {
            float4 a0 = *(const float4*)&As[buf][kk][ty*4];
            float4 b0 = *(const float4*)&Bs[buf][kk][tx*4];
            float av[4] = {a0.x,a0.y,a0.z,a0.w};
            float bv[4] = {b0.x,b0.y,b0.z,b0.w};
            #pragma unroll
            for (int i = 0; i < 4; i++)
                #pragma unroll
                for (int j = 0; j < 4; j++)
                    acc[i][j] += av[i]*bv[j];
        }
        __syncthreads();
    }

    #pragma unroll
    for (int i = 0; i < 4; i++) {
        int r = row0 + ty*4 + i;
        if (r >= M) continue;
        long long crow = sCr ? (long long)sCr[r]*ldc : (long long)r*ldc;
        #pragma unroll
        for (int j = 0; j < 4; j++) {
            int c = col0 + tx*4 + j;
            if (c >= N) continue;
            float v = acc[i][j];
            if (epi == 1 || epi == 3) v += bias[c];
            if (epi == 2) v = tanhf(v);
            if (epi == 3) v = sigf(v);
            Cb[crow + c] = v;
        }
    }
}

// ---------------- input build ----------------
__global__ void k_build_X(const int* __restrict__ code_x, const int* __restrict__ neigh,
                          const float* __restrict__ c_emb, const float* __restrict__ n_emb)
{
    int idx = blockIdx.x * blockDim.x + threadIdx.x;
    if (idx >= Nn * XCOLS) return;
    int n  = idx / XCOLS;
    int r  = idx % XCOLS;
    int bt = r / CSc;
    int c  = r % CSc;
    float cx = (float)code_x[bt*Nn + n];
    float nx = (float)neigh [bt*Nn + n];
    g_X[idx] = cx * c_emb[n*CSc + c] + nx * n_emb[n*CSc + c];
}

__global__ __launch_bounds__(288) void k_spmm(const float* __restrict__ adj)
{
    int m = blockIdx.x;
    int tid = threadIdx.x;
    __shared__ float arow[Nn];
    for (int i = tid; i < Nn; i += 288) arow[i] = adj[(long long)m*Nn + i];
    __syncthreads();
    float acc0 = 0.f, acc1 = 0.f, acc2 = 0.f, acc3 = 0.f;
    for (int n = 0; n < Nn; n++) {
        float a = arow[n];
        if (a != 0.f) {
            const float* xr = g_X + (long long)n * XCOLS;
            acc0 += a * xr[tid];
            acc1 += a * xr[tid + 288];
            acc2 += a * xr[tid + 576];
            acc3 += a * xr[tid + 864];
        }
    }
    float* sr = g_S + (long long)m * XCOLS;
    sr[tid] = acc0; sr[tid+288] = acc1; sr[tid+576] = acc2; sr[tid+864] = acc3;
}

__global__ void k_masks(const int* __restrict__ divided)
{
    int i = blockIdx.x * blockDim.x + threadIdx.x;
    if (i >= BT*Nn) return;
    g_m1 [i] = (divided[3*i]     > 0) ? 1 : 0;
    g_m23[i] = (divided[3*i + 1] > 0 || divided[3*i + 2] > 0) ? 1 : 0;
}

__global__ __launch_bounds__(1024) void k_compact()
{
    int z = blockIdx.x;
    int bt = ZBT(z);
    int n = threadIdx.x;
    __shared__ int warpCnt[32];
    int m = g_m23[bt*Nn + n];
    unsigned bal = __ballot_sync(0xffffffffu, m != 0);
    int lane = n & 31, w = n >> 5;
    int pre = __popc(bal & ((1u << lane) - 1u));
    if (lane == 0) warpCnt[w] = __popc(bal);
    __syncthreads();
    if (w == 0) {
        int v = warpCnt[lane];
        #pragma unroll
        for (int o = 1; o < 32; o <<= 1) {
            int u = __shfl_up_sync(0xffffffffu, v, o);
            if (lane >= o) v += u;
        }
        warpCnt[lane] = v;
    }
    __syncthreads();
    int base = (w == 0) ? 0 : warpCnt[w - 1];
    if (m) g_idx[z*Nn + base + pre] = n;
    if (n == 1023) g_cnt[z] = warpCnt[31];
}

__global__ __launch_bounds__(1024) void k_compact1()
{
    int bt = blockIdx.x;
    int n = threadIdx.x;
    __shared__ int warpCnt[32];
    int m = g_m1[bt*Nn + n];
    unsigned bal = __ballot_sync(0xffffffffu, m != 0);
    int lane = n & 31, w = n >> 5;
    int pre = __popc(bal & ((1u << lane) - 1u));
    if (lane == 0) warpCnt[w] = __popc(bal);
    __syncthreads();
    if (w == 0) {
        int v = warpCnt[lane];
        #pragma unroll
        for (int o = 1; o < 32; o <<= 1) {
            int u = __shfl_up_sync(0xffffffffu, v, o);
            if (lane >= o) v += u;
        }
        warpCnt[lane] = v;
    }
    __syncthreads();
    int base = (w == 0) ? 0 : warpCnt[w - 1];
    if (m) g_idx1[bt*Nn + base + pre] = n;
    if (n == 1023) g_cnt1[bt] = warpCnt[31];
}

__global__ __launch_bounds__(1024) void k_compact1t()
{
    int t = blockIdx.x;
    int n = threadIdx.x;
    int lane = n & 31, w = n >> 5;
    __shared__ int warpCnt[32];
    __shared__ int baseAcc;
    if (n == 0) baseAcc = 0;
    __syncthreads();
    for (int b = 0; b < Bb; b++) {
        int bt = b*Tt + t;
        int m = g_m1[bt*Nn + n];
        unsigned bal = __ballot_sync(0xffffffffu, m != 0);
        int pre = __popc(bal & ((1u << lane) - 1u));
        if (lane == 0) warpCnt[w] = __popc(bal);
        __syncthreads();
        if (w == 0) {
            int v = warpCnt[lane];
            #pragma unroll
            for (int o = 1; o < 32; o <<= 1) {
                int u = __shfl_up_sync(0xffffffffu, v, o);
                if (lane >= o) v += u;
            }
            warpCnt[lane] = v;
        }
        __syncthreads();
        int base = baseAcc + ((w == 0) ? 0 : warpCnt[w - 1]);
        if (m) g_idx1t[t*(Bb*Nn) + base + pre] = b*Nn + n;
        __syncthreads();
        if (n == 0) baseAcc += warpCnt[31];
        __syncthreads();
    }
    if (n == 0) g_c1t[t] = baseAcc;
}

__global__ void k_co_no(const int* __restrict__ code_x, const int* __restrict__ neigh,
                        const float* __restrict__ c_emb, const float* __restrict__ n_emb,
                        const float* __restrict__ Wg, const float* __restrict__ bg)
{
    int bt = blockIdx.x;
    int n  = blockIdx.y * 8 + threadIdx.y;
    int g  = threadIdx.x;
    __shared__ float Wgs[CSc][GSg];
    int tid = threadIdx.y * 32 + threadIdx.x;
    for (int i = tid; i < CSc*GSg; i += 256) Wgs[i / GSg][i % GSg] = Wg[i];
    __syncthreads();
    const float* Srow = g_S + (long long)n * XCOLS + bt * CSc;
    float a1 = 0.f, a2 = 0.f;
    #pragma unroll
    for (int c = 0; c < CSc; c++) {
        float s = Srow[c];
        float w = Wgs[c][g];
        a1 += (c_emb[n*CSc + c] + s) * w;
        a2 += (n_emb[n*CSc + c] + s) * w;
    }
    float cx = (float)code_x[bt*Nn + n];
    float nx = (float)neigh [bt*Nn + n];
    float co = cx * a1 + bg[g];
    float no = nx * a2 + bg[g];
    co = (co >= 0.f) ? co : 0.01f * co;
    no = (no >= 0.f) ? no : 0.01f * no;
    long long o = ((long long)bt*Nn + n) * GSg + g;
    g_co[o] = co;
    g_no[o] = no;
}

__global__ void k_qin(const int* __restrict__ divided, const float* __restrict__ u_emb)
{
    int idx = blockIdx.x * blockDim.x + threadIdx.x;
    if (idx >= BT*Nn*GSg) return;
    int g  = idx % GSg;
    int bn = idx / GSg;
    int n  = bn % Nn;
    int bt = bn / Nn;
    int t  = bt % Tt;
    float v;
    if (divided[bn*3 + 2] > 0)       v = u_emb[n*GSg + g];
    else if (t > 0)                  v = g_no[((long long)(bt-1)*Nn + n)*GSg + g];
    else                             v = 0.f;
    g_qin[idx] = v;
}

__global__ void k_packKV(const float* __restrict__ Wk, const float* __restrict__ bk,
                         const float* __restrict__ Wv, const float* __restrict__ bv)
{
    int idx = blockIdx.x * blockDim.x + threadIdx.x;
    if (idx >= 33*KV2) return;
    int r = idx / KV2, c = idx % KV2;
    float v;
    if (r < 32) {
        if (c < 32) v = Wk[r*ATa + c];
        else        v = Wv[r*Hh + (c - 32)];
    } else {
        if (c < 32) v = bk[c];
        else        v = bv[c - 32];
    }
    g_packKV[idx] = v;
}

__global__ void k_packWhh(const float* __restrict__ Whh)
{
    int idx = blockIdx.x * blockDim.x + threadIdx.x;
    if (idx >= Hh*H4) return;
    int g = idx & 3;
    int rem = idx >> 2;
    int j = rem % Hh;
    int k2 = rem / Hh;
    g_W4[idx] = Whh[k2*H4 + g*Hh + j];
}

// ---------------- fused compacted score + softmax (exp + rsum; no scale) ----------------
__global__ __launch_bounds__(256) void k_score_softmax()
{
    int z = blockIdx.y;
    int cq = g_cnt[z];
    int qr0 = blockIdx.x * 64;
    if (qr0 >= cq) return;
    const float* qp = g_q + (long long)z*Nn*ATa;
    const float* kb = g_kv + (long long)z*Nn*KV2;
    float* G = g_G + (long long)z * Nn * Nn;

    __shared__ float qs[64][33];
    __shared__ float ks[64][33];
    __shared__ float pmax[16][64];
    __shared__ float rowmax[64];

    int tid = threadIdx.x;
    int tx = tid & 15, ty = tid >> 4;

    for (int i = tid; i < 64*32; i += 256) {
        int r = i >> 5, a = i & 31;
        int gq = qr0 + r;
        qs[r][a] = (gq < cq) ? qp[(long long)gq*ATa + a] : 0.f;
    }

    float tmax[4] = {-1e30f, -1e30f, -1e30f, -1e30f};
    const float scale = 0.17677669529663687f;

    for (int j0 = 0; j0 < cq; j0 += 64) {
        __syncthreads();
        for (int i = tid; i < 64*32; i += 256) {
            int r = i >> 5, a = i & 31;
            int gk = j0 + r;
            ks[r][a] = (gk < cq) ? kb[(long long)gk*KV2 + a] : 0.f;
        }
        __syncthreads();
        float acc[4][4] = {};
        #pragma unroll
        for (int a = 0; a < 32; a++) {
            float av[4], bv[4];
            #pragma unroll
            for (int i = 0; i < 4; i++) av[i] = qs[ty*4+i][a];
            #pragma unroll
            for (int j = 0; j < 4; j++) bv[j] = ks[tx*4+j][a];
            #pragma unroll
            for (int i = 0; i < 4; i++)
                #pragma unroll
                for (int j = 0; j < 4; j++) acc[i][j] += av[i]*bv[j];
        }
        #pragma unroll
        for (int i = 0; i < 4; i++) {
            int gr = qr0 + ty*4 + i;
            if (gr >= cq) continue;
            #pragma unroll
            for (int j = 0; j < 4; j++) {
                int gc = j0 + tx*4 + j;
                if (gc >= cq) continue;
                float v = acc[i][j] * scale;
                G[(long long)gr*Nn + gc] = v;
                tmax[i] = fmaxf(tmax[i], v);
            }
        }
    }
    #pragma unroll
    for (int i = 0; i < 4; i++) pmax[tx][ty*4 + i] = tmax[i];
    __syncthreads();
    if (tid < 64) {
        float m = -1e30f;
        #pragma unroll
        for (int x = 0; x < 16; x++) m = fmaxf(m, pmax[x][tid]);
        rowmax[tid] = m;
    }
    __syncthreads();

    // exp pass + row-sum store (normalization deferred to PV epilogue)
    int row = tid >> 2, l4 = tid & 3;
    int gr = qr0 + row;
    float s = 0.f;
    if (gr < cq) {
        float m = rowmax[row];
        for (int c = l4; c < cq; c += 4) {
            float e = expf(G[(long long)gr*Nn + c] - m);
            G[(long long)gr*Nn + c] = e;
            s += e;
        }
    }
    s += __shfl_xor_sync(0xffffffffu, s, 1);
    s += __shfl_xor_sync(0xffffffffu, s, 2);
    if (gr < cq && l4 == 0)
        g_rsum[z*Nn + gr] = s;
}

// ---------------- GRU combine ----------------
__global__ void k_gru_combine(int t, const float* __restrict__ gbhh)
{
    int idx = blockIdx.x * blockDim.x + threadIdx.x;
    if (idx >= Bb*Nn*Hh) return;
    int j  = idx % Hh;
    int bn = idx / Hh;
    int n  = bn % Nn;
    int b  = bn / Nn;
    int bt = b*Tt + t;
    int mi = bt*Nn + n;
    float hv = 0.f;
    if (t > 0 && g_m23[mi]) {
        hv = g_hm23[((long long)(b*(Tt-1) + (t-1))*Nn + n) * Hh + j];
    } else if (g_m1[mi]) {
        const float* gir = g_gi + ((long long)bt*Nn + n)*H3;
        float g0, g1, g2;
        if (t == 0) { g0 = gbhh[j]; g1 = gbhh[Hh + j]; g2 = gbhh[2*Hh + j]; }
        else {
            const float* ghr = g_gh + (long long)bn * H3;
            g0 = ghr[j]; g1 = ghr[Hh + j]; g2 = ghr[2*Hh + j];
        }
        float r  = sigf(gir[j]        + g0);
        float zz = sigf(gir[Hh + j]   + g1);
        float nn = tanhf(gir[2*Hh + j] + r * g2);
        float hp = (t == 0) ? 0.f : g_h[idx];
        hv = (1.f - zz) * nn + zz * hp;
    }
    g_h[idx] = hv;
}

// parallel outlast
__global__ __launch_bounds__(288) void k_outlast1()
{
    int b = blockIdx.x, p = blockIdx.y, j = threadIdx.x;
    if (j >= Hh) return;
    float mx1 = -1e38f, mx23 = -1e38f;
    int mbase = (b*Tt + (Tt-1)) * Nn;
    int n0 = p * 64;
    for (int n = n0; n < n0 + 64; n++) {
        float hv = g_h[((long long)b*Nn + n)*Hh + j];
        if (g_m1 [mbase + n]) mx1  = fmaxf(mx1,  hv);
        if (g_m23[mbase + n]) mx23 = fmaxf(mx23, hv);
    }
    g_opart[((b*16 + p)*2    )*Hh + j] = mx1;
    g_opart[((b*16 + p)*2 + 1)*Hh + j] = mx23;
}

__global__ __launch_bounds__(288) void k_outlast2()
{
    int b = blockIdx.x, j = threadIdx.x;
    if (j >= Hh) return;
    float mx1 = -1e38f, mx23 = -1e38f;
    #pragma unroll
    for (int p = 0; p < 16; p++) {
        mx1  = fmaxf(mx1,  g_opart[((b*16 + p)*2    )*Hh + j]);
        mx23 = fmaxf(mx23, g_opart[((b*16 + p)*2 + 1)*Hh + j]);
    }
    float o = 0.f;
    if (mx1  > -1e37f) o += mx1;
    if (mx23 > -1e37f) o += mx23;
    g_stack[(long long)b*(Ee+1)*Hh + j] = o;
}

// ---------------- event LSTM ----------------
__global__ void k_evgather(const int* __restrict__ events, const float* __restrict__ Eemb)
{
    int idx = blockIdx.x * blockDim.x + threadIdx.x;
    if (idx >= Bb*Ee*Ll*EDd) return;
    int d   = idx % EDd;
    int rem = idx / EDd;
    int l   = rem % Ll;
    int be  = rem / Ll;
    int b   = be / Ee, e = be % Ee;
    int ev  = events[((b*Tt + (Tt-1))*Ee + e)*Ll + l];
    g_xe[idx] = Eemb[(long long)ev*EDd + d];
}

// column-parallel persistent LSTM (k-split, LDG.128 W loads, giL2 prefetch)
#define LB9 9
__global__ __launch_bounds__(544) void k_lstm3()
{
    __shared__ __align__(8)  float2 h2[Hh];
    __shared__ __align__(16) float4 a_sh[2][2][Hh];
    int tid = threadIdx.x;
    int row0 = blockIdx.x * 2;

    int mg, mj;
    if (tid < Hh)                    { mg = 0; mj = tid; }
    else if (tid >= 272 && tid < 542){ mg = 1; mj = tid - 272; }
    else                             { mg = -1; mj = 0; }

    int er = tid / Hh;
    int ej = tid - er * Hh;
    float cs = 0.f;

    if (tid < Hh) h2[tid] = make_float2(0.f, 0.f);
    __syncthreads();

    const float4* W4v = (const float4*)g_W4;
    int kbase = mg * 135;

    for (int l = 0; l < Ll; l++) {
        float4 gl = make_float4(0.f, 0.f, 0.f, 0.f);
        if (tid < 2*Hh)
            gl = *(const float4*)&g_giL2[(((long long)(row0 + er)*Ll + l)*Hh + ej)*4];

        if (mg >= 0) {
            float4 acc0 = make_float4(0.f,0.f,0.f,0.f);
            float4 acc1 = make_float4(0.f,0.f,0.f,0.f);
            #pragma unroll
            for (int k0 = 0; k0 < 135; k0 += LB9) {
                float4 wv[LB9];
                float2 hv[LB9];
                #pragma unroll
                for (int u = 0; u < LB9; u++) wv[u] = __ldg(&W4v[(long long)(kbase + k0 + u)*Hh + mj]);
                #pragma unroll
                for (int u = 0; u < LB9; u++) hv[u] = h2[kbase + k0 + u];
                #pragma unroll
                for (int u = 0; u < LB9; u++) {
                    acc0.x += hv[u].x*wv[u].x; acc0.y += hv[u].x*wv[u].y;
                    acc0.z += hv[u].x*wv[u].z; acc0.w += hv[u].x*wv[u].w;
                    acc1.x += hv[u].y*wv[u].x; acc1.y += hv[u].y*wv[u].y;
                    acc1.z += hv[u].y*wv[u].z; acc1.w += hv[u].y*wv[u].w;
                }
            }
            a_sh[mg][0][mj] = acc0;
            a_sh[mg][1][mj] = acc1;
        }
        __syncthreads();
        if (tid < 2*Hh) {
            float4 pa = a_sh[0][er][ej];
            float4 pb = a_sh[1][er][ej];
            float gi_ = pa.x + pb.x + gl.x;
            float gf  = pa.y + pb.y + gl.y;
            float gg  = pa.z + pb.z + gl.z;
            float go  = pa.w + pb.w + gl.w;
            cs = sigf(gf)*cs + sigf(gi_)*tanhf(gg);
            float hn = sigf(go)*tanhf(cs);
            float* hp = (float*)&h2[ej];
            hp[er] = hn;
        }
        __syncthreads();
    }

    if (tid < 2*Hh) {
        int be = row0 + er;
        int b = be / Ee, e = be % Ee;
        float* hp = (float*)&h2[ej];
        g_stack[((long long)b*(Ee+1) + 1 + e)*Hh + ej] = hp[er];
    }
}

// ---------------- final dp attention + head ----------------
__global__ void k_wdctx(const float* __restrict__ Wd, const float* __restrict__ bd,
                        const float* __restrict__ ctx)
{
    int j = threadIdx.x;
    if (j < Hh) {
        float s = 0.f;
        for (int d = 0; d < DAd; d++) s += Wd[j*DAd + d] * ctx[d];
        g_wdc[j] = s;
    } else if (j == Hh) {
        float s = 0.f;
        for (int d = 0; d < DAd; d++) s += bd[d] * ctx[d];
        g_wdc[Hh] = s;
    }
}

__global__ void k_dp1()
{
    int b = blockIdx.x, s = blockIdx.y;
    const float* x = g_stack + ((long long)b*(Ee+1) + s) * Hh;
    __shared__ float red[256];
    int tid = threadIdx.x;
    float acc = 0.f;
    for (int h = tid; h < Hh; h += 256) acc += x[h] * g_wdc[h];
    red[tid] = acc; __syncthreads();
    for (int st = 128; st > 0; st >>= 1) { if (tid < st) red[tid] += red[tid + st]; __syncthreads(); }
    if (tid == 0) g_vu[b*(Ee+1) + s] = red[0] + g_wdc[Hh];
}

__global__ void k_dp2()
{
    int b = blockIdx.x, j = threadIdx.x;
    __shared__ float sm[Ee+1];
    if (j == 0) {
        float mx = -1e38f;
        for (int s = 0; s < Ee+1; s++) mx = fmaxf(mx, g_vu[b*(Ee+1) + s]);
        float sum = 0.f;
        for (int s = 0; s < Ee+1; s++) { float e = expf(g_vu[b*(Ee+1) + s] - mx); sm[s] = e; sum += e; }
        float inv = 1.f / sum;
        for (int s = 0; s < Ee+1; s++) sm[s] *= inv;
    }
    __syncthreads();
    if (j < Hh) {
        float acc = 0.f;
        for (int s = 0; s < Ee+1; s++) acc += sm[s] * g_stack[((long long)b*(Ee+1) + s)*Hh + j];
        g_o1[b*Hh + j] = acc;
    }
}

// ---------------- host driver ----------------
extern "C" void kernel_launch(void* const* d_in, const int* in_sizes, int n_in,
                              void* d_out, int out_size)
{
    const int*   code_x = (const int*)  d_in[0];
    const int*   divided= (const int*)  d_in[1];
    const int*   neigh  = (const int*)  d_in[2];
    const int*   events = (const int*)  d_in[4];
    const float* c_emb  = (const float*)d_in[5];
    const float* n_emb  = (const float*)d_in[6];
    const float* u_emb  = (const float*)d_in[7];
    const float* adj    = (const float*)d_in[8];
    const float* Wg     = (const float*)d_in[9];
    const float* bg     = (const float*)d_in[10];
    const float* gWih   = (const float*)d_in[11];
    const float* gWhh   = (const float*)d_in[12];
    const float* gbih   = (const float*)d_in[13];
    const float* gbhh   = (const float*)d_in[14];
    const float* Wq     = (const float*)d_in[15];
    const float* bq     = (const float*)d_in[16];
    const float* Wk     = (const float*)d_in[17];
    const float* bk     = (const float*)d_in[18];
    const float* Wv     = (const float*)d_in[19];
    const float* bv     = (const float*)d_in[20];
    const float* Wd     = (const float*)d_in[21];
    const float* bd     = (const float*)d_in[22];
    const float* ctx    = (const float*)d_in[23];
    const float* Eemb   = (const float*)d_in[24];
    const float* lWih   = (const float*)d_in[25];
    const float* lWhh   = (const float*)d_in[26];
    const float* lb     = (const float*)d_in[27];
    const float* Wc     = (const float*)d_in[28];
    const float* bc     = (const float*)d_in[29];
    float* out = (float*)d_out;

    float *pco, *pqin, *pq, *pkv, *pgi, *pKV, *pG, *phm, *ph, *pgh, *pxe, *pgiL2, *po1, *prs;
    int *pidx, *pcnt, *pidx1, *pcnt1, *pidx1t, *pc1t;
    cudaGetSymbolAddress((void**)&pco,   g_co);
    cudaGetSymbolAddress((void**)&pqin,  g_qin);
    cudaGetSymbolAddress((void**)&pq,    g_q);
    cudaGetSymbolAddress((void**)&pkv,   g_kv);
    cudaGetSymbolAddress((void**)&pgi,   g_gi);
    cudaGetSymbolAddress((void**)&pKV,   g_packKV);
    cudaGetSymbolAddress((void**)&pG,    g_G);
    cudaGetSymbolAddress((void**)&phm,   g_hm23);
    cudaGetSymbolAddress((void**)&ph,    g_h);
    cudaGetSymbolAddress((void**)&pgh,   g_gh);
    cudaGetSymbolAddress((void**)&pxe,   g_xe);
    cudaGetSymbolAddress((void**)&pgiL2, g_giL2);
    cudaGetSymbolAddress((void**)&po1,   g_o1);
    cudaGetSymbolAddress((void**)&prs,   g_rsum);
    cudaGetSymbolAddress((void**)&pidx,  g_idx);
    cudaGetSymbolAddress((void**)&pcnt,  g_cnt);
    cudaGetSymbolAddress((void**)&pidx1, g_idx1);
    cudaGetSymbolAddress((void**)&pcnt1, g_cnt1);
    cudaGetSymbolAddress((void**)&pidx1t,g_idx1t);
    cudaGetSymbolAddress((void**)&pc1t,  g_c1t);

    static cudaStream_t s2 = 0;
    static cudaEvent_t evF = 0, evJ = 0;
    if (!s2) {
        cudaStreamCreateWithFlags(&s2, cudaStreamNonBlocking);
        cudaEventCreateWithFlags(&evF, cudaEventDisableTiming);
        cudaEventCreateWithFlags(&evJ, cudaEventDisableTiming);
    }

    // main stream: throughput-heavy opening phase (uncontended)
    k_build_X<<<(Nn*XCOLS + 255)/256, 256>>>(code_x, neigh, c_emb, n_emb);
    k_masks  <<<(BT*Nn + 255)/256, 256>>>(divided);
    k_wdctx  <<<1, 288>>>(Wd, bd, ctx);
    k_compact  <<<BT2, 1024>>>();
    k_compact1 <<<BT,  1024>>>();
    k_compact1t<<<Tt,  1024>>>();
    k_packKV<<<(33*KV2 + 255)/256, 256>>>(Wk, bk, Wv, bv);

    k_spmm<<<Nn, 288>>>(adj);
    k_co_no<<<dim3(BT, Nn/8), dim3(32,8)>>>(code_x, neigh, c_emb, n_emb, Wg, bg);
    k_qin  <<<(BT*Nn*GSg + 255)/256, 256>>>(divided, u_emb);

    // gi projection: m1 rows only, scattered
    k_gemm<<<dim3(13, 8, BT), 256>>>(pco, gWih, gbih, pgi,
        Nn, H3, GSg, GSg, H3, H3,
        (long long)Nn*GSg, 0, (long long)Nn*H3,
        1, 0,0, pidx1, Nn, 0,0, pidx1, Nn, pcnt1, 0, 0);

    // k|v projection: m23 rows only (t>=1), stored COMPACT
    k_gemm<<<dim3(5, 8, BT2), 256>>>(pco, pKV, pKV + 32*KV2, pkv,
        Nn, KV2, GSg, GSg, KV2, KV2,
        (long long)Nn*GSg, 0, (long long)Nn*KV2,
        1, 1,0, pidx, Nn, 0,0, 0,0, pcnt, 0, 0);

    // late fork: s2 event-LSTM chain overlaps the latency-bound tail
    cudaEventRecord(evF, 0);
    cudaStreamWaitEvent(s2, evF, 0);
    k_packWhh<<<(Hh*H4 + 255)/256, 256, 0, s2>>>(lWhh);
    k_evgather<<<(Bb*Ee*Ll*EDd + 255)/256, 256, 0, s2>>>(events, Eemb);
    k_gemm<<<dim3(17, 32, 1), 256, 0, s2>>>(pxe, lWih, lb, pgiL2,
        Bb*Ee*Ll, H4, EDd, EDd, H4, H4, 0,0,0, 4, 0,0, 0,0, 0,0, 0,0, 0,0, 0);
    k_lstm3<<<(Bb*Ee)/2, 544, 0, s2>>>();
    cudaEventRecord(evJ, s2);

    // q projection, compact m23 rows
    k_gemm64<<<dim3(1, 16, BT2), 256>>>(pqin, Wq, bq, pq,
        Nn, ATa, GSg, GSg, ATa, ATa,
        (long long)Nn*GSg, 0, (long long)Nn*ATa,
        1, 1,0, pidx, Nn, 0,0, 0,0, pcnt, 0);

    // attention: score -> exp+rsum; PV epilogue normalizes + tanh
    k_score_softmax<<<dim3(16, BT2), 256>>>();
    k_gemm<<<dim3(5, 8, BT2), 256>>>(pG, pkv + 32, 0, phm,
        Nn, Hh, Nn, Nn, KV2, Hh,
        (long long)Nn*Nn, (long long)Nn*KV2, (long long)Nn*Hh,
        5, 0,0, 0,0, 0,0, pidx, Nn, pcnt, pcnt, prs);

    // GRU: t=0 bias-only; t>=1 gh GEMM compacted to m1 rows
    k_gru_combine<<<(Bb*Nn*Hh + 255)/256, 256>>>(0, gbhh);
    for (int t = 1; t < Tt; t++) {
        k_gemm64<<<dim3(13, 64, 1), 256>>>(ph, gWhh, gbhh, pgh,
            Bb*Nn, H3, Hh, Hh, H3, H3, 0,0,0,
            1, 0,0, pidx1t + t*(Bb*Nn), 0, 0,0, pidx1t + t*(Bb*Nn), 0, pc1t + t, 0);
        k_gru_combine<<<(Bb*Nn*Hh + 255)/256, 256>>>(t, gbhh);
    }
    k_outlast1<<<dim3(Bb, 16), 288>>>();
    k_outlast2<<<Bb, 288>>>();

    // join LSTM chain, then dp attention + classifier
    cudaStreamWaitEvent(0, evJ, 0);
    k_dp1<<<dim3(Bb, Ee+1), 256>>>();
    k_dp2<<<Bb, 288>>>();
    k_gemm64<<<dim3(63, 1, 1), 256>>>(po1, Wc, bc, out,
        Bb, OUTo, Hh, Hh, OUTo, OUTo, 0,0,0, 3, 0,0, 0,0, 0,0, 0,0, 0,0);
}